// round 7
// baseline (speedup 1.0000x reference)
#include <cuda_runtime.h>

#define BB 4
#define SS_DIM 1024
#define XX 1024
#define CC 8
#define DD 2
#define WIDTH 16
#define DEPTH 4
#define SCHUNK 32
#define TPB 128

typedef unsigned long long u64;

__device__ __forceinline__ u64 fma2(u64 a, u64 b, u64 c) {
    u64 d;
    asm("fma.rn.f32x2 %0, %1, %2, %3;" : "=l"(d) : "l"(a), "l"(b), "l"(c));
    return d;
}
__device__ __forceinline__ u64 dup2(float a) {
    u64 r; unsigned ai = __float_as_uint(a);
    asm("mov.b64 %0, {%1, %1};" : "=l"(r) : "r"(ai));
    return r;
}
__device__ __forceinline__ void unpack2(u64 v, float& a, float& b) {
    unsigned x, y;
    asm("mov.b64 {%0, %1}, %2;" : "=r"(x), "=r"(y) : "l"(v));
    a = __uint_as_float(x);
    b = __uint_as_float(y);
}
__device__ __forceinline__ float fast_tanh(float x) {
    float y;
    asm("tanh.approx.f32 %0, %1;" : "=f"(y) : "f"(x));
    return y;
}

__global__ __launch_bounds__(TPB, 2)
void ccl_kernel(const float* __restrict__ yu,
                const float* __restrict__ xin,
                const float* __restrict__ gWin,
                const float* __restrict__ gbin,
                const float* __restrict__ gWhid,
                const float* __restrict__ gbhid,
                const float* __restrict__ gWout,
                const float* __restrict__ gbout,
                float* __restrict__ out) {
    __shared__ u64 s_Whid[DEPTH][WIDTH][WIDTH / 2];  // j-pairs, 4KB
    __shared__ u64 s_bhid[DEPTH][WIDTH / 2];
    __shared__ u64 s_Win[WIDTH / 2];
    __shared__ u64 s_bin[WIDTH / 2];
    __shared__ float s_Wout[WIDTH];
    __shared__ float s_bout;
    __shared__ float s_y[SCHUNK][DD];
    __shared__ float s_u[SCHUNK][CC];

    const int t  = threadIdx.x;
    const int b  = blockIdx.z;
    const int s0 = blockIdx.y * SCHUNK;
    const int xi = blockIdx.x * TPB + t;

    {
        const u64* gW = (const u64*)gWhid;  // [4][16][16] = 512 u64
        for (int i = t; i < DEPTH * WIDTH * WIDTH / 2; i += TPB)
            ((u64*)s_Whid)[i] = gW[i];
        if (t < DEPTH * WIDTH / 2) ((u64*)s_bhid)[t] = ((const u64*)gbhid)[t];
        if (t < WIDTH / 2) {
            s_Win[t] = ((const u64*)gWin)[t];
            s_bin[t] = ((const u64*)gbin)[t];
        }
        if (t < WIDTH) s_Wout[t] = gWout[t];
        if (t == 0) s_bout = gbout[0];
        for (int i = t; i < SCHUNK * (CC + DD); i += TPB) {
            const int s = i / (CC + DD);
            const int c = i % (CC + DD);
            const float v = yu[((size_t)b * SS_DIM + (s0 + s)) * (CC + DD) + c];
            if (c < CC) s_u[s][c] = v;
            else        s_y[s][c - CC] = v;
        }
    }
    __syncthreads();

    const float2 xv = *reinterpret_cast<const float2*>(&xin[((size_t)b * XX + xi) * DD]);

    float acc[CC];
#pragma unroll
    for (int c = 0; c < CC; ++c) acc[c] = 0.0f;

#pragma unroll 1
    for (int ss0 = 0; ss0 < SCHUNK; ss0 += 2) {
        // h scalar per point (consumed as broadcast), z packed (f32x2 accumulate)
        float h0[WIDTH], h1[WIDTH];
        {
            float d0 = xv.x - s_y[ss0][0];
            float d1 = xv.y - s_y[ss0][1];
            const u64 r0 = dup2(fmaf(d1, d1, d0 * d0));
            d0 = xv.x - s_y[ss0 + 1][0];
            d1 = xv.y - s_y[ss0 + 1][1];
            const u64 r1 = dup2(fmaf(d1, d1, d0 * d0));
#pragma unroll
            for (int jp = 0; jp < WIDTH / 2; ++jp) {
                const u64 w = s_Win[jp], bi = s_bin[jp];
                unpack2(fma2(r0, w, bi), h0[2 * jp], h0[2 * jp + 1]);
                unpack2(fma2(r1, w, bi), h1[2 * jp], h1[2 * jp + 1]);
            }
        }

#pragma unroll
        for (int l = 0; l < DEPTH; ++l) {
            u64 z0[WIDTH / 2], z1[WIDTH / 2];
#pragma unroll
            for (int jp = 0; jp < WIDTH / 2; ++jp) {
                const u64 bi = s_bhid[l][jp];
                z0[jp] = bi;
                z1[jp] = bi;
            }
#pragma unroll
            for (int kk = 0; kk < WIDTH; ++kk) {
                const u64 a0 = dup2(h0[kk]);
                const u64 a1 = dup2(h1[kk]);
#pragma unroll
                for (int jp = 0; jp < WIDTH / 2; ++jp) {
                    const u64 w = s_Whid[l][kk][jp];   // one LDS.64 feeds both points
                    z0[jp] = fma2(a0, w, z0[jp]);
                    z1[jp] = fma2(a1, w, z1[jp]);
                }
            }
#pragma unroll
            for (int jp = 0; jp < WIDTH / 2; ++jp) {
                float za, zb;
                unpack2(z0[jp], za, zb);
                h0[2 * jp]     += fast_tanh(za);
                h0[2 * jp + 1] += fast_tanh(zb);
                unpack2(z1[jp], za, zb);
                h1[2 * jp]     += fast_tanh(za);
                h1[2 * jp + 1] += fast_tanh(zb);
            }
        }

        float k0 = s_bout, k1 = s_bout;
#pragma unroll
        for (int j = 0; j < WIDTH; ++j) {
            const float w = s_Wout[j];
            k0 = fmaf(h0[j], w, k0);
            k1 = fmaf(h1[j], w, k1);
        }

#pragma unroll
        for (int c = 0; c < CC; ++c) {
            acc[c] = fmaf(k0, s_u[ss0][c], acc[c]);
            acc[c] = fmaf(k1, s_u[ss0 + 1][c], acc[c]);
        }
    }

    const float invS = 1.0f / (float)SS_DIM;
    float* op = &out[((size_t)b * XX + xi) * CC];
#pragma unroll
    for (int c = 0; c < CC; ++c) atomicAdd(&op[c], acc[c] * invS);
}

extern "C" void kernel_launch(void* const* d_in, const int* in_sizes, int n_in,
                              void* d_out, int out_size) {
    const float* yu    = (const float*)d_in[0]; // (4,1024,10)
    const float* x     = (const float*)d_in[1]; // (4,1024,2)
    const float* W_in  = (const float*)d_in[2]; // (1,16)
    const float* b_in  = (const float*)d_in[3]; // (16,)
    const float* W_hid = (const float*)d_in[4]; // (4,16,16)
    const float* b_hid = (const float*)d_in[5]; // (4,16)
    const float* W_out = (const float*)d_in[6]; // (16,1)
    const float* b_out = (const float*)d_in[7]; // (1,)

    (void)in_sizes; (void)n_in;

    cudaMemsetAsync(d_out, 0, (size_t)out_size * sizeof(float), 0);

    dim3 grid(XX / TPB, SS_DIM / SCHUNK, BB);
    ccl_kernel<<<grid, TPB, 0, 0>>>(yu, x, W_in, b_in, W_hid, b_hid, W_out, b_out,
                                    (float*)d_out);
}

// round 8
// speedup vs baseline: 20.6539x; 20.6539x over previous
#include <cuda_runtime.h>
#include <cuda_bf16.h>

#define BB 4
#define SS_DIM 1024
#define XX 1024
#define CC 8
#define DD 2
#define WIDTH 16
#define DEPTH 4
#define TPB 128

__device__ __forceinline__ float fast_tanh(float x) {
    float y; asm("tanh.approx.f32 %0, %1;" : "=f"(y) : "f"(x)); return y;
}
// pack two f32 -> bf16x2, first arg in LOWER half
__device__ __forceinline__ unsigned pack_bf16x2(float lo, float hi) {
    unsigned d; asm("cvt.rn.bf16x2.f32 %0, %1, %2;" : "=r"(d) : "f"(hi), "f"(lo)); return d;
}
__device__ __forceinline__ float bf16lo_as_f32(unsigned p) { return __uint_as_float(p << 16); }
__device__ __forceinline__ float bf16hi_as_f32(unsigned p) { return __uint_as_float(p & 0xffff0000u); }

// split two f32 into packed bf16x2 (hi) and packed bf16x2 residual (lo)
__device__ __forceinline__ void split_pack(float e0, float e1, unsigned& hi, unsigned& lo) {
    hi = pack_bf16x2(e0, e1);
    lo = pack_bf16x2(e0 - bf16lo_as_f32(hi), e1 - bf16hi_as_f32(hi));
}

__device__ __forceinline__ void mma_bf16(float* c,  // c[4]
                                         const unsigned* a,  // a[4]
                                         unsigned b0, unsigned b1) {
    asm("mma.sync.aligned.m16n8k16.row.col.f32.bf16.bf16.f32 "
        "{%0,%1,%2,%3}, {%4,%5,%6,%7}, {%8,%9}, {%0,%1,%2,%3};"
        : "+f"(c[0]), "+f"(c[1]), "+f"(c[2]), "+f"(c[3])
        : "r"(a[0]), "r"(a[1]), "r"(a[2]), "r"(a[3]), "r"(b0), "r"(b1));
}

__global__ __launch_bounds__(TPB)
void ccl_kernel(const float* __restrict__ yu,
                const float* __restrict__ xin,
                const float* __restrict__ gWin,
                const float* __restrict__ gbin,
                const float* __restrict__ gWhid,
                const float* __restrict__ gbhid,
                const float* __restrict__ gWout,
                const float* __restrict__ gbout,
                float* __restrict__ out) {
    __shared__ float  s_u[SS_DIM][CC];   // 32KB
    __shared__ float2 s_y[SS_DIM];       // 8KB

    const int t    = threadIdx.x;
    const int warp = t >> 5;
    const int lane = t & 31;
    const int g    = lane >> 2;   // groupID (row within tile)
    const int q    = lane & 3;    // thread-in-group (col quad)
    const int b    = blockIdx.y;
    const int xi   = blockIdx.x * 4 + warp;

    // ---- stage yu[b] (all 1024 rows) into smem ----
    for (int i = t; i < SS_DIM; i += TPB) {
        const float2* row = (const float2*)(yu + ((size_t)b * SS_DIM + i) * (CC + DD));
        const float2 a0 = row[0], a1 = row[1], a2 = row[2], a3 = row[3], yv = row[4];
        float2* ur = (float2*)&s_u[i][0];
        ur[0] = a0; ur[1] = a1; ur[2] = a2; ur[3] = a3;
        s_y[i] = yv;
    }
    __syncthreads();

    // ---- per-lane register-resident weight fragments ----
    // column indices this lane touches: 2q, 2q+1, 8+2q, 9+2q
    const int j0 = 2 * q, j1 = 2 * q + 1, j2 = 8 + 2 * q, j3 = 9 + 2 * q;

    float winr[4] = {gWin[j0], gWin[j1], gWin[j2], gWin[j3]};
    float binr[4] = {gbin[j0], gbin[j1], gbin[j2], gbin[j3]};
    float wor[4]  = {gWout[j0], gWout[j1], gWout[j2], gWout[j3]};
    const float bout = gbout[0];

    float bb[DEPTH][4];
#pragma unroll
    for (int l = 0; l < DEPTH; ++l) {
        bb[l][0] = gbhid[l * WIDTH + j0];
        bb[l][1] = gbhid[l * WIDTH + j1];
        bb[l][2] = gbhid[l * WIDTH + j2];
        bb[l][3] = gbhid[l * WIDTH + j3];
    }

    // B fragments: Bhi/Blo[layer][nt][reg]; B(k,n) = W_hid[l][k][n]
    unsigned Bhi[DEPTH][2][2], Blo[DEPTH][2][2];
#pragma unroll
    for (int l = 0; l < DEPTH; ++l) {
        const float* Wl = gWhid + l * WIDTH * WIDTH;
#pragma unroll
        for (int nt = 0; nt < 2; ++nt) {
            const int n = g + 8 * nt;
            const float w00 = Wl[(2 * q) * WIDTH + n];
            const float w01 = Wl[(2 * q + 1) * WIDTH + n];
            const float w10 = Wl[(2 * q + 8) * WIDTH + n];
            const float w11 = Wl[(2 * q + 9) * WIDTH + n];
            split_pack(w00, w01, Bhi[l][nt][0], Blo[l][nt][0]);
            split_pack(w10, w11, Bhi[l][nt][1], Blo[l][nt][1]);
        }
    }

    const float2 xv = *(const float2*)(xin + ((size_t)b * XX + xi) * DD);

    float acc0 = 0.0f, acc1 = 0.0f;  // channels 2q, 2q+1

#pragma unroll 1
    for (int s0 = 0; s0 < SS_DIM; s0 += 32) {
        // r for this lane's s-point
        const float2 yv = s_y[s0 + lane];
        const float d0 = xv.x - yv.x;
        const float d1 = xv.y - yv.y;
        const float r = fmaf(d1, d1, d0 * d0);
        // rows this lane needs: g, g+8 (mt0), 16+g, 24+g (mt1)
        const float r0 = __shfl_sync(0xffffffffu, r, g);
        const float r1 = __shfl_sync(0xffffffffu, r, g + 8);
        const float r2 = __shfl_sync(0xffffffffu, r, g + 16);
        const float r3 = __shfl_sync(0xffffffffu, r, g + 24);

        // H in D-fragment layout: hD[mt][nt][c]
        float hD[2][2][4];
#pragma unroll
        for (int nt = 0; nt < 2; ++nt) {
            hD[0][nt][0] = fmaf(r0, winr[2 * nt], binr[2 * nt]);
            hD[0][nt][1] = fmaf(r0, winr[2 * nt + 1], binr[2 * nt + 1]);
            hD[0][nt][2] = fmaf(r1, winr[2 * nt], binr[2 * nt]);
            hD[0][nt][3] = fmaf(r1, winr[2 * nt + 1], binr[2 * nt + 1]);
            hD[1][nt][0] = fmaf(r2, winr[2 * nt], binr[2 * nt]);
            hD[1][nt][1] = fmaf(r2, winr[2 * nt + 1], binr[2 * nt + 1]);
            hD[1][nt][2] = fmaf(r3, winr[2 * nt], binr[2 * nt]);
            hD[1][nt][3] = fmaf(r3, winr[2 * nt + 1], binr[2 * nt + 1]);
        }

#pragma unroll
        for (int l = 0; l < DEPTH; ++l) {
            // A fragments from hD (identity layout mapping, no shuffles)
            unsigned ahi[2][4], alo[2][4];
#pragma unroll
            for (int mt = 0; mt < 2; ++mt) {
                split_pack(hD[mt][0][0], hD[mt][0][1], ahi[mt][0], alo[mt][0]);
                split_pack(hD[mt][0][2], hD[mt][0][3], ahi[mt][1], alo[mt][1]);
                split_pack(hD[mt][1][0], hD[mt][1][1], ahi[mt][2], alo[mt][2]);
                split_pack(hD[mt][1][2], hD[mt][1][3], ahi[mt][3], alo[mt][3]);
            }
            // Z = bias + Hhi*Whi + Hhi*Wlo + Hlo*Whi
#pragma unroll
            for (int mt = 0; mt < 2; ++mt) {
#pragma unroll
                for (int nt = 0; nt < 2; ++nt) {
                    float z[4] = {bb[l][2 * nt], bb[l][2 * nt + 1],
                                  bb[l][2 * nt], bb[l][2 * nt + 1]};
                    mma_bf16(z, ahi[mt], Bhi[l][nt][0], Bhi[l][nt][1]);
                    mma_bf16(z, ahi[mt], Blo[l][nt][0], Blo[l][nt][1]);
                    mma_bf16(z, alo[mt], Bhi[l][nt][0], Bhi[l][nt][1]);
#pragma unroll
                    for (int c = 0; c < 4; ++c)
                        hD[mt][nt][c] += fast_tanh(z[c]);
                }
            }
        }

        // k = h @ Wout + bout, per GEMM row; quad-reduce partials
        float k[4];
#pragma unroll
        for (int mt = 0; mt < 2; ++mt) {
            float pg  = fmaf(hD[mt][0][0], wor[0],
                        fmaf(hD[mt][0][1], wor[1],
                        fmaf(hD[mt][1][0], wor[2], hD[mt][1][1] * wor[3])));
            float pg8 = fmaf(hD[mt][0][2], wor[0],
                        fmaf(hD[mt][0][3], wor[1],
                        fmaf(hD[mt][1][2], wor[2], hD[mt][1][3] * wor[3])));
            pg  += __shfl_xor_sync(0xffffffffu, pg, 1);
            pg  += __shfl_xor_sync(0xffffffffu, pg, 2);
            pg8 += __shfl_xor_sync(0xffffffffu, pg8, 1);
            pg8 += __shfl_xor_sync(0xffffffffu, pg8, 2);
            k[2 * mt]     = pg + bout;
            k[2 * mt + 1] = pg8 + bout;
        }

        // acc[2q..2q+1] += k[s] * u[s][2q..2q+1], s = s0 + {g, g+8, 16+g, 24+g}
        const int srow[4] = {s0 + g, s0 + g + 8, s0 + 16 + g, s0 + 24 + g};
#pragma unroll
        for (int i = 0; i < 4; ++i) {
            const float2 uv = *(const float2*)&s_u[srow[i]][2 * q];
            acc0 = fmaf(k[i], uv.x, acc0);
            acc1 = fmaf(k[i], uv.y, acc1);
        }
    }

    // reduce over g (lanes with same q), then lanes 0-3 store 2 channels each
#pragma unroll
    for (int off = 4; off < 32; off <<= 1) {
        acc0 += __shfl_xor_sync(0xffffffffu, acc0, off);
        acc1 += __shfl_xor_sync(0xffffffffu, acc1, off);
    }
    if (lane < 4) {
        const float invS = 1.0f / (float)SS_DIM;
        float2 v = make_float2(acc0 * invS, acc1 * invS);
        *(float2*)(out + ((size_t)b * XX + xi) * CC + 2 * lane) = v;
    }
}

extern "C" void kernel_launch(void* const* d_in, const int* in_sizes, int n_in,
                              void* d_out, int out_size) {
    const float* yu    = (const float*)d_in[0]; // (4,1024,10)
    const float* x     = (const float*)d_in[1]; // (4,1024,2)
    const float* W_in  = (const float*)d_in[2]; // (1,16)
    const float* b_in  = (const float*)d_in[3]; // (16,)
    const float* W_hid = (const float*)d_in[4]; // (4,16,16)
    const float* b_hid = (const float*)d_in[5]; // (4,16)
    const float* W_out = (const float*)d_in[6]; // (16,1)
    const float* b_out = (const float*)d_in[7]; // (1,)

    (void)in_sizes; (void)n_in; (void)out_size;

    dim3 grid(XX / 4, BB, 1);   // 4 warps (xi) per block
    ccl_kernel<<<grid, TPB, 0, 0>>>(yu, x, W_in, b_in, W_hid, b_hid, W_out, b_out,
                                    (float*)d_out);
}

// round 9
// speedup vs baseline: 21.2640x; 1.0295x over previous
#include <cuda_runtime.h>
#include <cuda_bf16.h>

#define BB 4
#define SS_DIM 1024
#define XX 1024
#define CC 8
#define DD 2
#define WIDTH 16
#define DEPTH 4
#define TPB 128

__device__ __forceinline__ float fast_tanh(float x) {
    float y; asm("tanh.approx.f32 %0, %1;" : "=f"(y) : "f"(x)); return y;
}
// pack two f32 -> bf16x2, first arg in LOWER half
__device__ __forceinline__ unsigned pack_bf16x2(float lo, float hi) {
    unsigned d; asm("cvt.rn.bf16x2.f32 %0, %1, %2;" : "=r"(d) : "f"(hi), "f"(lo)); return d;
}
__device__ __forceinline__ float bf16lo_as_f32(unsigned p) { return __uint_as_float(p << 16); }
__device__ __forceinline__ float bf16hi_as_f32(unsigned p) { return __uint_as_float(p & 0xffff0000u); }

__device__ __forceinline__ void split_pack(float e0, float e1, unsigned& hi, unsigned& lo) {
    hi = pack_bf16x2(e0, e1);
    lo = pack_bf16x2(e0 - bf16lo_as_f32(hi), e1 - bf16hi_as_f32(hi));
}

// D = A*B + {c0,c1,c0,c1}   (bias as C operand, D written fresh — no init MOVs)
__device__ __forceinline__ void mma_bf16_init(float* d, const unsigned* a,
                                              unsigned b0, unsigned b1,
                                              float c0, float c1) {
    asm("mma.sync.aligned.m16n8k16.row.col.f32.bf16.bf16.f32 "
        "{%0,%1,%2,%3}, {%4,%5,%6,%7}, {%8,%9}, {%10,%11,%10,%11};"
        : "=f"(d[0]), "=f"(d[1]), "=f"(d[2]), "=f"(d[3])
        : "r"(a[0]), "r"(a[1]), "r"(a[2]), "r"(a[3]), "r"(b0), "r"(b1),
          "f"(c0), "f"(c1));
}
__device__ __forceinline__ void mma_bf16(float* c, const unsigned* a,
                                         unsigned b0, unsigned b1) {
    asm("mma.sync.aligned.m16n8k16.row.col.f32.bf16.bf16.f32 "
        "{%0,%1,%2,%3}, {%4,%5,%6,%7}, {%8,%9}, {%0,%1,%2,%3};"
        : "+f"(c[0]), "+f"(c[1]), "+f"(c[2]), "+f"(c[3])
        : "r"(a[0]), "r"(a[1]), "r"(a[2]), "r"(a[3]), "r"(b0), "r"(b1));
}

__global__ __launch_bounds__(TPB, 5)
void ccl_kernel(const float* __restrict__ yu,
                const float* __restrict__ xin,
                const float* __restrict__ gWin,
                const float* __restrict__ gbin,
                const float* __restrict__ gWhid,
                const float* __restrict__ gbhid,
                const float* __restrict__ gWout,
                const float* __restrict__ gbout,
                float* __restrict__ out) {
    __shared__ float  s_u[SS_DIM][CC];      // 32KB
    __shared__ float2 s_y[SS_DIM];          // 8KB
    __shared__ float  s_bias[DEPTH][WIDTH]; // 256B
    __shared__ float  s_win[WIDTH];
    __shared__ float  s_bin[WIDTH];
    __shared__ float  s_wout[WIDTH];

    const int t    = threadIdx.x;
    const int warp = t >> 5;
    const int lane = t & 31;
    const int g    = lane >> 2;   // groupID (row within tile)
    const int q    = lane & 3;    // thread-in-group (col quad)
    const int b    = blockIdx.y;
    const int xi   = blockIdx.x * 4 + warp;

    // ---- stage yu[b] + small weights into smem ----
    for (int i = t; i < SS_DIM; i += TPB) {
        const float2* row = (const float2*)(yu + ((size_t)b * SS_DIM + i) * (CC + DD));
        const float2 a0 = row[0], a1 = row[1], a2 = row[2], a3 = row[3], yv = row[4];
        float2* ur = (float2*)&s_u[i][0];
        ur[0] = a0; ur[1] = a1; ur[2] = a2; ur[3] = a3;
        s_y[i] = yv;
    }
    if (t < DEPTH * WIDTH) ((float*)s_bias)[t] = gbhid[t];
    if (t < WIDTH) {
        s_win[t]  = gWin[t];
        s_bin[t]  = gbin[t];
        s_wout[t] = gWout[t];
    }
    __syncthreads();

    const float bout = gbout[0];

    // ---- register-resident B fragments: B(k,n) = W_hid[l][k][n], 2-term bf16 split ----
    unsigned Bhi[DEPTH][2][2], Blo[DEPTH][2][2];
#pragma unroll
    for (int l = 0; l < DEPTH; ++l) {
        const float* Wl = gWhid + l * WIDTH * WIDTH;
#pragma unroll
        for (int nt = 0; nt < 2; ++nt) {
            const int n = g + 8 * nt;
            const float w00 = Wl[(2 * q) * WIDTH + n];
            const float w01 = Wl[(2 * q + 1) * WIDTH + n];
            const float w10 = Wl[(2 * q + 8) * WIDTH + n];
            const float w11 = Wl[(2 * q + 9) * WIDTH + n];
            split_pack(w00, w01, Bhi[l][nt][0], Blo[l][nt][0]);
            split_pack(w10, w11, Bhi[l][nt][1], Blo[l][nt][1]);
        }
    }

    const float2 xv = *(const float2*)(xin + ((size_t)b * XX + xi) * DD);

    float acc0 = 0.0f, acc1 = 0.0f;  // output channels 2q, 2q+1

#pragma unroll 1
    for (int s0 = 0; s0 < SS_DIM; s0 += 32) {
        // r for this lane's s-point, then gather the 4 rows this lane owns in fragments
        const float2 yv = s_y[s0 + lane];
        const float dx0 = xv.x - yv.x;
        const float dx1 = xv.y - yv.y;
        const float r = fmaf(dx1, dx1, dx0 * dx0);
        const float r0 = __shfl_sync(0xffffffffu, r, g);
        const float r1 = __shfl_sync(0xffffffffu, r, g + 8);
        const float r2 = __shfl_sync(0xffffffffu, r, g + 16);
        const float r3 = __shfl_sync(0xffffffffu, r, g + 24);

        // per-lane W_in/b_in column pairs (j0,j1)=(2q,2q+1), (j2,j3)=(8+2q,9+2q)
        const float2 wA  = ((const float2*)s_win)[q];
        const float2 wB  = ((const float2*)(s_win + 8))[q];
        const float2 biA = ((const float2*)s_bin)[q];
        const float2 biB = ((const float2*)(s_bin + 8))[q];

        // H in D-fragment layout: hD[mt][nt][c]
        float hD[2][2][4];
#pragma unroll
        for (int nt = 0; nt < 2; ++nt) {
            const float2 wv = nt ? wB : wA;
            const float2 bv = nt ? biB : biA;
            hD[0][nt][0] = fmaf(r0, wv.x, bv.x);
            hD[0][nt][1] = fmaf(r0, wv.y, bv.y);
            hD[0][nt][2] = fmaf(r1, wv.x, bv.x);
            hD[0][nt][3] = fmaf(r1, wv.y, bv.y);
            hD[1][nt][0] = fmaf(r2, wv.x, bv.x);
            hD[1][nt][1] = fmaf(r2, wv.y, bv.y);
            hD[1][nt][2] = fmaf(r3, wv.x, bv.x);
            hD[1][nt][3] = fmaf(r3, wv.y, bv.y);
        }

#pragma unroll
        for (int l = 0; l < DEPTH; ++l) {
            const float2 bhA = ((const float2*)&s_bias[l][0])[q];
            const float2 bhB = ((const float2*)&s_bias[l][8])[q];
#pragma unroll
            for (int mt = 0; mt < 2; ++mt) {
                unsigned ahi[4], alo[4];
                split_pack(hD[mt][0][0], hD[mt][0][1], ahi[0], alo[0]);
                split_pack(hD[mt][0][2], hD[mt][0][3], ahi[1], alo[1]);
                split_pack(hD[mt][1][0], hD[mt][1][1], ahi[2], alo[2]);
                split_pack(hD[mt][1][2], hD[mt][1][3], ahi[3], alo[3]);
#pragma unroll
                for (int nt = 0; nt < 2; ++nt) {
                    float z[4];
                    mma_bf16_init(z, ahi, Bhi[l][nt][0], Bhi[l][nt][1],
                                  nt ? bhB.x : bhA.x, nt ? bhB.y : bhA.y);
                    mma_bf16(z, ahi, Blo[l][nt][0], Blo[l][nt][1]);
                    mma_bf16(z, alo, Bhi[l][nt][0], Bhi[l][nt][1]);
#pragma unroll
                    for (int c = 0; c < 4; ++c)
                        hD[mt][nt][c] += fast_tanh(z[c]);
                }
            }
        }

        // k = h @ Wout + bout per GEMM row; quad-reduce
        const float2 woA = ((const float2*)s_wout)[q];
        const float2 woB = ((const float2*)(s_wout + 8))[q];
        float k[4];
#pragma unroll
        for (int mt = 0; mt < 2; ++mt) {
            float pg  = fmaf(hD[mt][0][0], woA.x,
                        fmaf(hD[mt][0][1], woA.y,
                        fmaf(hD[mt][1][0], woB.x, hD[mt][1][1] * woB.y)));
            float pg8 = fmaf(hD[mt][0][2], woA.x,
                        fmaf(hD[mt][0][3], woA.y,
                        fmaf(hD[mt][1][2], woB.x, hD[mt][1][3] * woB.y)));
            pg  += __shfl_xor_sync(0xffffffffu, pg, 1);
            pg  += __shfl_xor_sync(0xffffffffu, pg, 2);
            pg8 += __shfl_xor_sync(0xffffffffu, pg8, 1);
            pg8 += __shfl_xor_sync(0xffffffffu, pg8, 2);
            k[2 * mt]     = pg + bout;
            k[2 * mt + 1] = pg8 + bout;
        }

        const int srow[4] = {s0 + g, s0 + g + 8, s0 + 16 + g, s0 + 24 + g};
#pragma unroll
        for (int i = 0; i < 4; ++i) {
            const float2 uv = *(const float2*)&s_u[srow[i]][2 * q];
            acc0 = fmaf(k[i], uv.x, acc0);
            acc1 = fmaf(k[i], uv.y, acc1);
        }
    }

#pragma unroll
    for (int off = 4; off < 32; off <<= 1) {
        acc0 += __shfl_xor_sync(0xffffffffu, acc0, off);
        acc1 += __shfl_xor_sync(0xffffffffu, acc1, off);
    }
    if (lane < 4) {
        const float invS = 1.0f / (float)SS_DIM;
        float2 v = make_float2(acc0 * invS, acc1 * invS);
        *(float2*)(out + ((size_t)b * XX + xi) * CC + 2 * lane) = v;
    }
}

extern "C" void kernel_launch(void* const* d_in, const int* in_sizes, int n_in,
                              void* d_out, int out_size) {
    const float* yu    = (const float*)d_in[0]; // (4,1024,10)
    const float* x     = (const float*)d_in[1]; // (4,1024,2)
    const float* W_in  = (const float*)d_in[2]; // (1,16)
    const float* b_in  = (const float*)d_in[3]; // (16,)
    const float* W_hid = (const float*)d_in[4]; // (4,16,16)
    const float* b_hid = (const float*)d_in[5]; // (4,16)
    const float* W_out = (const float*)d_in[6]; // (16,1)
    const float* b_out = (const float*)d_in[7]; // (1,)

    (void)in_sizes; (void)n_in; (void)out_size;

    dim3 grid(XX / 4, BB, 1);   // 4 warps (xi) per block
    ccl_kernel<<<grid, TPB, 0, 0>>>(yu, x, W_in, b_in, W_hid, b_hid, W_out, b_out,
                                    (float*)d_out);
}